// round 11
// baseline (speedup 1.0000x reference)
#include <cuda_runtime.h>
#include <cuda_bf16.h>
#include <cstdint>

// Problem constants
#define BATCH 64
#define OUTF  8192
#define INF   8192
#define RANK  16
#define GROUP 16
#define KC    64
#define NCHUNK (INF / KC)          // 128
#define NCHUNK_HALF (NCHUNK / 2)   // 64 per split-K CTA
#define OUT_TILE 64
#define NOTILES (OUTF / OUT_TILE)  // 128
#define NBLOCKS (2 * NOTILES)      // 256

#define WS_STRIDE 68               // W_s row stride: conflict-free A reads + STS.128

// scratch: lora t (64x16), tf32-rounded fragment-permuted x^T (2MB), split-K partials (4MB)
__device__ float g_t[BATCH * RANK];
__device__ __align__(16) float g_xt[INF * BATCH];   // [k][p], p = fragment-permuted batch
__device__ __align__(16) float g_p[2 * BATCH * OUTF];

__device__ __forceinline__ unsigned tf32_rna(float x) {
    unsigned r;
    asm("cvt.rna.tf32.f32 %0, %1;" : "=r"(r) : "f"(x));
    return r;
}
__device__ __forceinline__ float tf32f(float x) {
    return __uint_as_float(tf32_rna(x));
}

// nvfp4 (e2m1) nibble -> fp32, times scale. n in [0,16).
__device__ __forceinline__ float dec4(unsigned n, float scr) {
    unsigned m = n & 7u;
    unsigned man = (m & ((m >> 1) | (m >> 2))) & 1u;
    unsigned bits = ((126u + (m >> 1)) << 23) | (man << 22);
    if (m == 0u) bits = 0u;
    bits |= (n & 8u) << 28;
    return __uint_as_float(bits) * scr;
}

__device__ __forceinline__ void mma_tf32_16x8x8(
    float& c0, float& c1, float& c2, float& c3,
    unsigned a0, unsigned a1, unsigned a2, unsigned a3,
    unsigned b0, unsigned b1)
{
    asm volatile(
        "mma.sync.aligned.m16n8k8.row.col.f32.tf32.tf32.f32 "
        "{%0,%1,%2,%3}, {%4,%5,%6,%7}, {%8,%9}, {%0,%1,%2,%3};"
        : "+f"(c0), "+f"(c1), "+f"(c2), "+f"(c3)
        : "r"(a0), "r"(a1), "r"(a2), "r"(a3), "r"(b0), "r"(b1));
}

// ---------------------------------------------------------------------------
// Prep kernel (fused):
//  blocks [0,64):    t[b][r] = sum_i x[b][i] * A[r][i]        (fp32 exact)
//  blocks [64,192):  g_xt[k][p] = tf32(x[perm(p)][k]) for one 64-k slab,
//    where permuted col p = 32h + 4g + j holds batch 32h + 8j + g
//    (so a B-fragment j-quad is one contiguous float4)
// ---------------------------------------------------------------------------
__global__ __launch_bounds__(256) void prep_kernel(
    const float* __restrict__ x, const float* __restrict__ A)
{
    __shared__ float ts[64][65];
    const int tid = threadIdx.x;

    if (blockIdx.x < BATCH) {
        const int b = blockIdx.x;
        const int r = tid & 15;
        const int part = tid >> 4;

        const float* xr = x + (size_t)b * INF + part * 512;
        const float* ar = A + (size_t)r * INF + part * 512;

        float s0 = 0.f, s1 = 0.f, s2 = 0.f, s3 = 0.f;
        #pragma unroll 2
        for (int j = 0; j < 512; j += 16) {
            #pragma unroll
            for (int u = 0; u < 4; u++) {
                float4 xv = *reinterpret_cast<const float4*>(xr + j + 4 * u);
                float4 av = *reinterpret_cast<const float4*>(ar + j + 4 * u);
                float d = xv.x * av.x + xv.y * av.y + xv.z * av.z + xv.w * av.w;
                if (u == 0) s0 += d; else if (u == 1) s1 += d;
                else if (u == 2) s2 += d; else s3 += d;
            }
        }
        float* red = &ts[0][0];
        red[tid] = (s0 + s1) + (s2 + s3);
        __syncthreads();
        if (tid < 16) {
            float t = 0.0f;
            #pragma unroll
            for (int p = 0; p < 16; p++) t += red[p * 16 + tid];
            g_t[b * RANK + tid] = t;
        }
    } else {
        const int k0 = (blockIdx.x - BATCH) * 64;
        const int b = tid >> 2;
        const int q = tid & 3;
        const float4* x4 = reinterpret_cast<const float4*>(x);

        #pragma unroll
        for (int p = 0; p < 4; p++) {
            float4 v = x4[(size_t)b * (INF / 4) + (k0 >> 2) + q * 4 + p];
            const int kk = q * 16 + p * 4;
            ts[kk + 0][b] = v.x;
            ts[kk + 1][b] = v.y;
            ts[kk + 2][b] = v.z;
            ts[kk + 3][b] = v.w;
        }
        __syncthreads();

        // write fragment-permuted, tf32-rounded
        float4* out4 = reinterpret_cast<float4*>(g_xt) + (size_t)(blockIdx.x - BATCH) * 1024;
        #pragma unroll
        for (int p = 0; p < 4; p++) {
            const int f = tid + 256 * p;
            const int k = f >> 4;
            const int col4 = f & 15;              // float4 index in row: perm base p0 = 4*col4
            const int h = (col4 >> 3) * 32;       // batch half
            const int g = col4 & 7;               // gid
            out4[f] = make_float4(tf32f(ts[k][h + 0 + g]),   // j=0 -> batch h+0*8+g
                                  tf32f(ts[k][h + 8 + g]),
                                  tf32f(ts[k][h + 16 + g]),
                                  tf32f(ts[k][h + 24 + g]));
        }
    }
}

// ---------------------------------------------------------------------------
// Main kernel: split-K=2 dequant + tf32 mma, double-buffered W smem,
// B fragments loaded directly from fragment-permuted g_xt (L1/L2-hot).
//  grid = 256: blockIdx = otile | (khalf << 7). 256 threads (8 warps).
// ---------------------------------------------------------------------------
__global__ __launch_bounds__(256, 2) void qlora_main_kernel(
    const int* __restrict__ pw,        // one packed BYTE per int32 element
    const float* __restrict__ sc,
    const float* __restrict__ lB)
{
    __shared__ float W_s[2][OUT_TILE * WS_STRIDE];   // 34.8 KB
    __shared__ float lb_s[OUT_TILE * RANK];
    __shared__ float t_s[BATCH * RANK];

    const int tid   = threadIdx.x;
    const int lane  = tid & 31;
    const int warp  = tid >> 5;
    const int otile = blockIdx.x & (NOTILES - 1);
    const int khalf = blockIdx.x >> 7;
    const int o0    = otile * OUT_TILE;

    // ---- W staging roles (conflict-free STS.128 phases) ----
    const int wg   = (tid >> 3) & 3;
    const int wrow = (tid & 7) | ((tid >> 5) << 3);
    const int* pw_row = pw + (size_t)(o0 + wrow) * (INF / 2)
                           + (size_t)khalf * (INF / 4) + wg * 8;
    const float* sc_row = sc + (size_t)(o0 + wrow) * (INF / GROUP)
                             + khalf * (INF / (2 * GROUP)) + wg;

    // warp tiling
    const int m0  = (warp & 3) * 16;
    const int nb  = (warp >> 2) * 32;
    const int gid = lane >> 2;
    const int tig = lane & 3;
    const int boff = nb + 4 * gid;                 // permuted B column base

    const float* xk_base = g_xt + (size_t)(khalf * (INF / 2)) * 64;

    float acc[4][4];
    #pragma unroll
    for (int j = 0; j < 4; j++)
        #pragma unroll
        for (int e = 0; e < 4; e++) acc[j][e] = 0.0f;

    // ---- prologue: decode chunk 0 into stage 0, prefetch codes for chunk 1 ----
    uint4 pa = *reinterpret_cast<const uint4*>(pw_row);
    uint4 pb = *reinterpret_cast<const uint4*>(pw_row + 4);
    float scr = sc_row[0];
    {
        unsigned codes[8] = { pa.x, pa.y, pa.z, pa.w, pb.x, pb.y, pb.z, pb.w };
        float wv[16];
        #pragma unroll
        for (int j = 0; j < 8; j++) {
            const unsigned cb = codes[j] & 0xFFu;
            wv[2 * j]     = tf32f(dec4(cb & 15u, scr));
            wv[2 * j + 1] = tf32f(dec4(cb >> 4, scr));
        }
        float* wdst = &W_s[0][wrow * WS_STRIDE + wg * 16];
        #pragma unroll
        for (int q = 0; q < 4; q++)
            *reinterpret_cast<float4*>(wdst + q * 4) =
                make_float4(wv[q * 4], wv[q * 4 + 1], wv[q * 4 + 2], wv[q * 4 + 3]);
    }
    pa = *reinterpret_cast<const uint4*>(pw_row + (KC / 2));
    pb = *reinterpret_cast<const uint4*>(pw_row + (KC / 2) + 4);
    scr = sc_row[KC / GROUP];
    __syncthreads();

    for (int c = 0; c < NCHUNK_HALF; c++) {
        // ---- MMA phase: A from W_s[c&1], B via LDG from permuted g_xt ----
        const float* Wbuf = W_s[c & 1];
        const float* xc = xk_base + (size_t)c * KC * 64;
        #pragma unroll
        for (int s = 0; s < 8; s++) {
            const int kl = s * 8;
            unsigned a0 = __float_as_uint(Wbuf[(m0 + gid) * WS_STRIDE + kl + tig]);
            unsigned a1 = __float_as_uint(Wbuf[(m0 + gid + 8) * WS_STRIDE + kl + tig]);
            unsigned a2 = __float_as_uint(Wbuf[(m0 + gid) * WS_STRIDE + kl + tig + 4]);
            unsigned a3 = __float_as_uint(Wbuf[(m0 + gid + 8) * WS_STRIDE + kl + tig + 4]);
            const float* bp = xc + (size_t)(kl + tig) * 64 + boff;
            float4 b0v = *reinterpret_cast<const float4*>(bp);
            float4 b1v = *reinterpret_cast<const float4*>(bp + 256);   // k + 4 rows
            mma_tf32_16x8x8(acc[0][0], acc[0][1], acc[0][2], acc[0][3],
                            a0, a1, a2, a3, __float_as_uint(b0v.x), __float_as_uint(b1v.x));
            mma_tf32_16x8x8(acc[1][0], acc[1][1], acc[1][2], acc[1][3],
                            a0, a1, a2, a3, __float_as_uint(b0v.y), __float_as_uint(b1v.y));
            mma_tf32_16x8x8(acc[2][0], acc[2][1], acc[2][2], acc[2][3],
                            a0, a1, a2, a3, __float_as_uint(b0v.z), __float_as_uint(b1v.z));
            mma_tf32_16x8x8(acc[3][0], acc[3][1], acc[3][2], acc[3][3],
                            a0, a1, a2, a3, __float_as_uint(b0v.w), __float_as_uint(b1v.w));
        }

        // ---- decode chunk c+1 into the other stage (overlaps MMA drain) ----
        if (c + 1 < NCHUNK_HALF) {
            unsigned codes[8] = { pa.x, pa.y, pa.z, pa.w, pb.x, pb.y, pb.z, pb.w };
            float wv[16];
            #pragma unroll
            for (int j = 0; j < 8; j++) {
                const unsigned cb = codes[j] & 0xFFu;
                wv[2 * j]     = tf32f(dec4(cb & 15u, scr));
                wv[2 * j + 1] = tf32f(dec4(cb >> 4, scr));
            }
            float* wdst = &W_s[(c + 1) & 1][wrow * WS_STRIDE + wg * 16];
            #pragma unroll
            for (int q = 0; q < 4; q++)
                *reinterpret_cast<float4*>(wdst + q * 4) =
                    make_float4(wv[q * 4], wv[q * 4 + 1], wv[q * 4 + 2], wv[q * 4 + 3]);

            if (c + 2 < NCHUNK_HALF) {
                const int* pn = pw_row + (c + 2) * (KC / 2);
                pa = *reinterpret_cast<const uint4*>(pn);
                pb = *reinterpret_cast<const uint4*>(pn + 4);
                scr = sc_row[(c + 2) * (KC / GROUP)];
            }
        }
        __syncthreads();
    }

    // ---- epilogue ----
    float* pout = g_p + (size_t)khalf * BATCH * OUTF;

    if (khalf == 0) {
        for (int i = tid; i < OUT_TILE * RANK; i += 256) {
            lb_s[i] = lB[(size_t)o0 * RANK + i];
            t_s[i]  = g_t[i];
        }
        __syncthreads();

        float lbr0[RANK], lbr1[RANK];
        #pragma unroll
        for (int r = 0; r < RANK; r++) {
            lbr0[r] = lb_s[(m0 + gid) * RANK + r];
            lbr1[r] = lb_s[(m0 + gid + 8) * RANK + r];
        }

        #pragma unroll
        for (int j = 0; j < 4; j++) {
            const int bc0 = nb + 8 * j + 2 * tig;
            const int bc1 = bc0 + 1;
            float d00 = 0.f, d01 = 0.f, d10 = 0.f, d11 = 0.f;
            #pragma unroll
            for (int r = 0; r < RANK; r++) {
                const float t0 = t_s[bc0 * RANK + r];
                const float t1 = t_s[bc1 * RANK + r];
                d00 += t0 * lbr0[r];
                d01 += t1 * lbr0[r];
                d10 += t0 * lbr1[r];
                d11 += t1 * lbr1[r];
            }
            const int og0 = o0 + m0 + gid;
            pout[(size_t)bc0 * OUTF + og0]     = acc[j][0] + d00;
            pout[(size_t)bc1 * OUTF + og0]     = acc[j][1] + d01;
            pout[(size_t)bc0 * OUTF + og0 + 8] = acc[j][2] + d10;
            pout[(size_t)bc1 * OUTF + og0 + 8] = acc[j][3] + d11;
        }
    } else {
        #pragma unroll
        for (int j = 0; j < 4; j++) {
            const int bc0 = nb + 8 * j + 2 * tig;
            const int bc1 = bc0 + 1;
            const int og0 = o0 + m0 + gid;
            pout[(size_t)bc0 * OUTF + og0]     = acc[j][0];
            pout[(size_t)bc1 * OUTF + og0]     = acc[j][1];
            pout[(size_t)bc0 * OUTF + og0 + 8] = acc[j][2];
            pout[(size_t)bc1 * OUTF + og0 + 8] = acc[j][3];
        }
    }
}

// ---------------------------------------------------------------------------
// Reduce kernel: out = p0 + p1 (elementwise, float4)
// ---------------------------------------------------------------------------
__global__ __launch_bounds__(256) void reduce_kernel(float* __restrict__ out)
{
    const int i = blockIdx.x * 256 + threadIdx.x;      // float4 index
    const float4* p0 = reinterpret_cast<const float4*>(g_p);
    const float4* p1 = p0 + (BATCH * OUTF) / 4;
    float4 a = p0[i];
    float4 b = p1[i];
    reinterpret_cast<float4*>(out)[i] =
        make_float4(a.x + b.x, a.y + b.y, a.z + b.z, a.w + b.w);
}

// ---------------------------------------------------------------------------
// launch
// inputs: x f32(64,8192), packed_weight int32(8192,4096) [byte per element],
//   weight_block_scales f32(8192,512), lora_A f32(16,8192), lora_B f32(8192,16)
// output: f32 (64,8192)
// ---------------------------------------------------------------------------
extern "C" void kernel_launch(void* const* d_in, const int* in_sizes, int n_in,
                              void* d_out, int out_size)
{
    const float* x   = (const float*)d_in[0];
    const int*   pw  = (const int*)d_in[1];
    const float* sc  = (const float*)d_in[2];
    const float* lA  = (const float*)d_in[3];
    const float* lB  = (const float*)d_in[4];
    float*       out = (float*)d_out;

    prep_kernel<<<BATCH + NCHUNK, 256>>>(x, lA);
    qlora_main_kernel<<<NBLOCKS, 256>>>(pw, sc, lB);
    reduce_kernel<<<(BATCH * OUTF / 4) / 256, 256>>>(out);
}

// round 12
// speedup vs baseline: 1.6135x; 1.6135x over previous
#include <cuda_runtime.h>
#include <cuda_bf16.h>
#include <cstdint>

// Problem constants
#define BATCH 64
#define OUTF  8192
#define INF   8192
#define RANK  16
#define GROUP 16
#define KC    64
#define NCHUNK (INF / KC)          // 128
#define NCHUNK_HALF (NCHUNK / 2)   // 64 per split-K CTA
#define OUT_TILE 64
#define NOTILES (OUTF / OUT_TILE)  // 128
#define NBLOCKS (2 * NOTILES)      // 256

#define WS_STRIDE 68               // W_s row stride: conflict-free A reads + STS.128
#define XS_STRIDE 72               // x_s row stride: conflict-free LDS.128 B reads
#define WS_FLOATS (OUT_TILE * WS_STRIDE)   // 4352 floats per stage
#define XS_FLOATS (KC * XS_STRIDE)         // 4608 floats per stage
#define MAIN_SMEM ((2 * WS_FLOATS + 2 * XS_FLOATS) * 4)   // 71680 B dynamic

// scratch: lora t (64x16), tf32-rounded fragment-permuted x^T (2MB), split-K partials (4MB)
__device__ float g_t[BATCH * RANK];
__device__ __align__(16) float g_xt[INF * BATCH];   // [k][p], p = fragment-permuted batch
__device__ __align__(16) float g_p[2 * BATCH * OUTF];

__device__ __forceinline__ unsigned tf32_rna(float x) {
    unsigned r;
    asm("cvt.rna.tf32.f32 %0, %1;" : "=r"(r) : "f"(x));
    return r;
}
__device__ __forceinline__ float tf32f(float x) {
    return __uint_as_float(tf32_rna(x));
}

// nvfp4 (e2m1) nibble -> fp32, times scale. n in [0,16).
__device__ __forceinline__ float dec4(unsigned n, float scr) {
    unsigned m = n & 7u;
    unsigned man = (m & ((m >> 1) | (m >> 2))) & 1u;
    unsigned bits = ((126u + (m >> 1)) << 23) | (man << 22);
    if (m == 0u) bits = 0u;
    bits |= (n & 8u) << 28;
    return __uint_as_float(bits) * scr;
}

__device__ __forceinline__ void mma_tf32_16x8x8(
    float& c0, float& c1, float& c2, float& c3,
    unsigned a0, unsigned a1, unsigned a2, unsigned a3,
    unsigned b0, unsigned b1)
{
    asm volatile(
        "mma.sync.aligned.m16n8k8.row.col.f32.tf32.tf32.f32 "
        "{%0,%1,%2,%3}, {%4,%5,%6,%7}, {%8,%9}, {%0,%1,%2,%3};"
        : "+f"(c0), "+f"(c1), "+f"(c2), "+f"(c3)
        : "r"(a0), "r"(a1), "r"(a2), "r"(a3), "r"(b0), "r"(b1));
}

// ---------------------------------------------------------------------------
// Prep kernel (512 threads):
//  blocks [0,64):    t[b][r] = sum_i x[b][i] * A[r][i]   (fp32, 32-way split)
//  blocks [64,192):  g_xt[k][p] = tf32(x[perm(p)][k]) for one 64-k slab,
//    permuted col p = 32h + 4g + j holds batch 32h + 8j + g
// ---------------------------------------------------------------------------
__global__ __launch_bounds__(512) void prep_kernel(
    const float* __restrict__ x, const float* __restrict__ A)
{
    __shared__ float ts[64][65];
    const int tid = threadIdx.x;

    if (blockIdx.x < BATCH) {
        const int b = blockIdx.x;
        const int r = tid & 15;
        const int part = tid >> 4;          // 0..31, 256 elems each

        const float* xr = x + (size_t)b * INF + part * 256;
        const float* ar = A + (size_t)r * INF + part * 256;

        float s0 = 0.f, s1 = 0.f, s2 = 0.f, s3 = 0.f;
        #pragma unroll 4
        for (int j = 0; j < 256; j += 16) {
            #pragma unroll
            for (int u = 0; u < 4; u++) {
                float4 xv = *reinterpret_cast<const float4*>(xr + j + 4 * u);
                float4 av = *reinterpret_cast<const float4*>(ar + j + 4 * u);
                float d = xv.x * av.x + xv.y * av.y + xv.z * av.z + xv.w * av.w;
                if (u == 0) s0 += d; else if (u == 1) s1 += d;
                else if (u == 2) s2 += d; else s3 += d;
            }
        }
        float* red = &ts[0][0];
        red[tid] = (s0 + s1) + (s2 + s3);
        __syncthreads();
        if (tid < 16) {
            float t = 0.0f;
            #pragma unroll
            for (int p = 0; p < 32; p++) t += red[p * 16 + tid];
            g_t[b * RANK + tid] = t;
        }
    } else {
        const int k0 = (blockIdx.x - BATCH) * 64;
        const int b = tid >> 3;             // 0..63
        const int q = tid & 7;              // 0..7 -> float4 cols 2q, 2q+1
        const float4* x4 = reinterpret_cast<const float4*>(x);

        #pragma unroll
        for (int p = 0; p < 2; p++) {
            const int fp = 2 * q + p;
            float4 v = x4[(size_t)b * (INF / 4) + (k0 >> 2) + fp];
            const int kk = fp * 4;
            ts[kk + 0][b] = v.x;
            ts[kk + 1][b] = v.y;
            ts[kk + 2][b] = v.z;
            ts[kk + 3][b] = v.w;
        }
        __syncthreads();

        float4* out4 = reinterpret_cast<float4*>(g_xt) + (size_t)(blockIdx.x - BATCH) * 1024;
        #pragma unroll
        for (int p = 0; p < 2; p++) {
            const int f = tid + 512 * p;
            const int k = f >> 4;
            const int col4 = f & 15;
            const int h = (col4 >> 3) * 32;
            const int g = col4 & 7;
            out4[f] = make_float4(tf32f(ts[k][h + 0 + g]),
                                  tf32f(ts[k][h + 8 + g]),
                                  tf32f(ts[k][h + 16 + g]),
                                  tf32f(ts[k][h + 24 + g]));
        }
    }
}

// ---------------------------------------------------------------------------
// Main kernel: split-K=2, double-buffered W_s AND x_s, ONE sync per chunk.
//  grid = 256: blockIdx = otile | (khalf << 7). 256 threads (8 warps).
//  Per iter: MMA(stage c&1) -> decode+stage (c+1)&1 from regs -> LDG c+2 -> sync.
// ---------------------------------------------------------------------------
__global__ __launch_bounds__(256, 2) void qlora_main_kernel(
    const int* __restrict__ pw,        // one packed BYTE per int32 element
    const float* __restrict__ sc,
    const float* __restrict__ lB)
{
    extern __shared__ float dsm[];
    float* Wbase = dsm;                        // 2 stages of WS_FLOATS
    float* Xbase = dsm + 2 * WS_FLOATS;        // 2 stages of XS_FLOATS
    __shared__ float lb_s[OUT_TILE * RANK];
    __shared__ float t_s[BATCH * RANK];

    const int tid   = threadIdx.x;
    const int lane  = tid & 31;
    const int warp  = tid >> 5;
    const int otile = blockIdx.x & (NOTILES - 1);
    const int khalf = blockIdx.x >> 7;
    const int o0    = otile * OUT_TILE;

    // ---- W staging roles (conflict-free STS.128 phases) ----
    const int wg   = (tid >> 3) & 3;
    const int wrow = (tid & 7) | ((tid >> 5) << 3);
    const int* pw_row = pw + (size_t)(o0 + wrow) * (INF / 2)
                           + (size_t)khalf * (INF / 4) + wg * 8;
    const float* sc_row = sc + (size_t)(o0 + wrow) * (INF / GROUP)
                             + khalf * (INF / (2 * GROUP)) + wg;
    float* wdst_base = Wbase + wrow * WS_STRIDE + wg * 16;

    // x staging: 4 float4s per thread per chunk
    const float4* xt4 = reinterpret_cast<const float4*>(g_xt)
                      + (size_t)khalf * NCHUNK_HALF * 1024;

    // warp tiling
    const int m0  = (warp & 3) * 16;
    const int nb  = (warp >> 2) * 32;
    const int gid = lane >> 2;
    const int tig = lane & 3;
    const int boff = nb + 4 * gid;             // permuted B column base

    float acc[4][4];
    #pragma unroll
    for (int j = 0; j < 4; j++)
        #pragma unroll
        for (int e = 0; e < 4; e++) acc[j][e] = 0.0f;

    // ---- prologue: stage chunk 0, prefetch chunk 1 into regs ----
    uint4 pa = *reinterpret_cast<const uint4*>(pw_row);
    uint4 pb = *reinterpret_cast<const uint4*>(pw_row + 4);
    float scr = sc_row[0];
    float4 xr[4];
    #pragma unroll
    for (int p = 0; p < 4; p++) xr[p] = xt4[tid + 256 * p];
    {
        unsigned codes[8] = { pa.x, pa.y, pa.z, pa.w, pb.x, pb.y, pb.z, pb.w };
        float wv[16];
        #pragma unroll
        for (int j = 0; j < 8; j++) {
            const unsigned cb = codes[j] & 0xFFu;
            wv[2 * j]     = dec4(cb & 15u, scr);   // mma.tf32 truncates low bits
            wv[2 * j + 1] = dec4(cb >> 4, scr);
        }
        #pragma unroll
        for (int q = 0; q < 4; q++)
            *reinterpret_cast<float4*>(wdst_base + q * 4) =
                make_float4(wv[q * 4], wv[q * 4 + 1], wv[q * 4 + 2], wv[q * 4 + 3]);
        #pragma unroll
        for (int p = 0; p < 4; p++) {
            const int f = tid + 256 * p;
            const int k = f >> 4;
            const int c4 = (f & 15) * 4;
            *reinterpret_cast<float4*>(&Xbase[k * XS_STRIDE + c4]) = xr[p];
        }
    }
    // prefetch chunk 1
    pa = *reinterpret_cast<const uint4*>(pw_row + (KC / 2));
    pb = *reinterpret_cast<const uint4*>(pw_row + (KC / 2) + 4);
    scr = sc_row[KC / GROUP];
    #pragma unroll
    for (int p = 0; p < 4; p++) xr[p] = xt4[1024 + tid + 256 * p];
    __syncthreads();

    for (int c = 0; c < NCHUNK_HALF; c++) {
        // ---- MMA phase on stage c&1 ----
        const float* Wbuf = Wbase + (c & 1) * WS_FLOATS;
        const float* Xbuf = Xbase + (c & 1) * XS_FLOATS;
        #pragma unroll
        for (int s = 0; s < 8; s++) {
            const int kl = s * 8;
            unsigned a0 = __float_as_uint(Wbuf[(m0 + gid) * WS_STRIDE + kl + tig]);
            unsigned a1 = __float_as_uint(Wbuf[(m0 + gid + 8) * WS_STRIDE + kl + tig]);
            unsigned a2 = __float_as_uint(Wbuf[(m0 + gid) * WS_STRIDE + kl + tig + 4]);
            unsigned a3 = __float_as_uint(Wbuf[(m0 + gid + 8) * WS_STRIDE + kl + tig + 4]);
            const float* bp = Xbuf + (kl + tig) * XS_STRIDE + boff;
            float4 b0v = *reinterpret_cast<const float4*>(bp);
            float4 b1v = *reinterpret_cast<const float4*>(bp + 4 * XS_STRIDE);
            mma_tf32_16x8x8(acc[0][0], acc[0][1], acc[0][2], acc[0][3],
                            a0, a1, a2, a3, __float_as_uint(b0v.x), __float_as_uint(b1v.x));
            mma_tf32_16x8x8(acc[1][0], acc[1][1], acc[1][2], acc[1][3],
                            a0, a1, a2, a3, __float_as_uint(b0v.y), __float_as_uint(b1v.y));
            mma_tf32_16x8x8(acc[2][0], acc[2][1], acc[2][2], acc[2][3],
                            a0, a1, a2, a3, __float_as_uint(b0v.z), __float_as_uint(b1v.z));
            mma_tf32_16x8x8(acc[3][0], acc[3][1], acc[3][2], acc[3][3],
                            a0, a1, a2, a3, __float_as_uint(b0v.w), __float_as_uint(b1v.w));
        }

        // ---- stage chunk c+1 into the other buffers (overlaps MMA drain) ----
        if (c + 1 < NCHUNK_HALF) {
            const int st = (c + 1) & 1;
            unsigned codes[8] = { pa.x, pa.y, pa.z, pa.w, pb.x, pb.y, pb.z, pb.w };
            float wv[16];
            #pragma unroll
            for (int j = 0; j < 8; j++) {
                const unsigned cb = codes[j] & 0xFFu;
                wv[2 * j]     = dec4(cb & 15u, scr);
                wv[2 * j + 1] = dec4(cb >> 4, scr);
            }
            float* wdst = wdst_base + st * WS_FLOATS;
            #pragma unroll
            for (int q = 0; q < 4; q++)
                *reinterpret_cast<float4*>(wdst + q * 4) =
                    make_float4(wv[q * 4], wv[q * 4 + 1], wv[q * 4 + 2], wv[q * 4 + 3]);
            float* xdst = Xbase + st * XS_FLOATS;
            #pragma unroll
            for (int p = 0; p < 4; p++) {
                const int f = tid + 256 * p;
                const int k = f >> 4;
                const int c4 = (f & 15) * 4;
                *reinterpret_cast<float4*>(&xdst[k * XS_STRIDE + c4]) = xr[p];
            }

            // ---- prefetch chunk c+2 into regs (global latency spans next iter) ----
            if (c + 2 < NCHUNK_HALF) {
                const int* pn = pw_row + (c + 2) * (KC / 2);
                pa = *reinterpret_cast<const uint4*>(pn);
                pb = *reinterpret_cast<const uint4*>(pn + 4);
                scr = sc_row[(c + 2) * (KC / GROUP)];
                const float4* src = xt4 + (size_t)(c + 2) * 1024;
                #pragma unroll
                for (int p = 0; p < 4; p++) xr[p] = src[tid + 256 * p];
            }
        }
        __syncthreads();
    }

    // ---- epilogue ----
    float* pout = g_p + (size_t)khalf * BATCH * OUTF;

    if (khalf == 0) {
        for (int i = tid; i < OUT_TILE * RANK; i += 256) {
            lb_s[i] = lB[(size_t)o0 * RANK + i];
            t_s[i]  = g_t[i];
        }
        __syncthreads();

        float lbr0[RANK], lbr1[RANK];
        #pragma unroll
        for (int r = 0; r < RANK; r++) {
            lbr0[r] = lb_s[(m0 + gid) * RANK + r];
            lbr1[r] = lb_s[(m0 + gid + 8) * RANK + r];
        }

        #pragma unroll
        for (int j = 0; j < 4; j++) {
            const int bc0 = nb + 8 * j + 2 * tig;
            const int bc1 = bc0 + 1;
            float d00 = 0.f, d01 = 0.f, d10 = 0.f, d11 = 0.f;
            #pragma unroll
            for (int r = 0; r < RANK; r++) {
                const float t0 = t_s[bc0 * RANK + r];
                const float t1 = t_s[bc1 * RANK + r];
                d00 += t0 * lbr0[r];
                d01 += t1 * lbr0[r];
                d10 += t0 * lbr1[r];
                d11 += t1 * lbr1[r];
            }
            const int og0 = o0 + m0 + gid;
            pout[(size_t)bc0 * OUTF + og0]     = acc[j][0] + d00;
            pout[(size_t)bc1 * OUTF + og0]     = acc[j][1] + d01;
            pout[(size_t)bc0 * OUTF + og0 + 8] = acc[j][2] + d10;
            pout[(size_t)bc1 * OUTF + og0 + 8] = acc[j][3] + d11;
        }
    } else {
        #pragma unroll
        for (int j = 0; j < 4; j++) {
            const int bc0 = nb + 8 * j + 2 * tig;
            const int bc1 = bc0 + 1;
            const int og0 = o0 + m0 + gid;
            pout[(size_t)bc0 * OUTF + og0]     = acc[j][0];
            pout[(size_t)bc1 * OUTF + og0]     = acc[j][1];
            pout[(size_t)bc0 * OUTF + og0 + 8] = acc[j][2];
            pout[(size_t)bc1 * OUTF + og0 + 8] = acc[j][3];
        }
    }
}

// ---------------------------------------------------------------------------
// Reduce kernel: out = p0 + p1 (elementwise, float4)
// ---------------------------------------------------------------------------
__global__ __launch_bounds__(256) void reduce_kernel(float* __restrict__ out)
{
    const int i = blockIdx.x * 256 + threadIdx.x;      // float4 index
    const float4* p0 = reinterpret_cast<const float4*>(g_p);
    const float4* p1 = p0 + (BATCH * OUTF) / 4;
    float4 a = p0[i];
    float4 b = p1[i];
    reinterpret_cast<float4*>(out)[i] =
        make_float4(a.x + b.x, a.y + b.y, a.z + b.z, a.w + b.w);
}

// ---------------------------------------------------------------------------
// launch
// inputs: x f32(64,8192), packed_weight int32(8192,4096) [byte per element],
//   weight_block_scales f32(8192,512), lora_A f32(16,8192), lora_B f32(8192,16)
// output: f32 (64,8192)
// ---------------------------------------------------------------------------
extern "C" void kernel_launch(void* const* d_in, const int* in_sizes, int n_in,
                              void* d_out, int out_size)
{
    const float* x   = (const float*)d_in[0];
    const int*   pw  = (const int*)d_in[1];
    const float* sc  = (const float*)d_in[2];
    const float* lA  = (const float*)d_in[3];
    const float* lB  = (const float*)d_in[4];
    float*       out = (float*)d_out;

    cudaFuncSetAttribute(qlora_main_kernel,
                         cudaFuncAttributeMaxDynamicSharedMemorySize, MAIN_SMEM);

    prep_kernel<<<BATCH + NCHUNK, 512>>>(x, lA);
    qlora_main_kernel<<<NBLOCKS, 256, MAIN_SMEM>>>(pw, sc, lB);
    reduce_kernel<<<(BATCH * OUTF / 4) / 256, 256>>>(out);
}